// round 16
// baseline (speedup 1.0000x reference)
#include <cuda_runtime.h>
#include <cstdint>

// ---------------------------------------------------------------------------
// Problem constants
// ---------------------------------------------------------------------------
#define DIMX   1024
#define NH     16
#define HD     64
#define BATCH  4
#define SEQ    2048
#define ROWS   (BATCH * SEQ)        // 8192
#define QKVD   (3 * DIMX)           // 3072
#define KH     (DIMX / 2)           // 512 u32 pairs per 1024 cols
#define KQ     (QKVD / 2)           // 1536 u32 pairs per qkv row

// ---------------------------------------------------------------------------
// Scratch (__device__ globals; allocation is forbidden)
// ---------------------------------------------------------------------------
__device__ float    g_qkv [(size_t)ROWS * QKVD];   // fp32 qkv (V section only)
__device__ uint32_t g_qkvh[(size_t)ROWS * KQ];     // qkv hi (Q pre-scaled)
__device__ uint32_t g_qkvl[(size_t)ROWS * KQ];     // qkv lo
__device__ uint32_t g_vth [(size_t)BATCH * NH * HD * (SEQ / 2)];  // V^T hi
__device__ uint32_t g_vtl [(size_t)BATCH * NH * HD * (SEQ / 2)];  // V^T lo
__device__ uint32_t g_xh  [(size_t)ROWS * KH];
__device__ uint32_t g_xl  [(size_t)ROWS * KH];
__device__ uint32_t g_wqh [(size_t)QKVD * KH];
__device__ uint32_t g_wql [(size_t)QKVD * KH];
__device__ uint32_t g_woh [(size_t)DIMX * KH];
__device__ uint32_t g_wol [(size_t)DIMX * KH];
__device__ uint32_t g_ah  [(size_t)ROWS * KH];     // attention out hi
__device__ uint32_t g_al  [(size_t)ROWS * KH];     // attention out lo

// ---------------------------------------------------------------------------
// helpers
// ---------------------------------------------------------------------------
__device__ __forceinline__ uint32_t smem_u32(const void* p) {
    uint32_t a;
    asm("{ .reg .u64 t; cvta.to.shared.u64 t, %1; cvt.u32.u64 %0, t; }"
        : "=r"(a) : "l"(p));
    return a;
}

__device__ __forceinline__ void split2(float x, float y, uint32_t& h, uint32_t& l) {
    asm("cvt.rn.bf16x2.f32 %0, %1, %2;" : "=r"(h) : "f"(y), "f"(x));
    float hx = __uint_as_float(h << 16);
    float hy = __uint_as_float(h & 0xFFFF0000u);
    asm("cvt.rn.bf16x2.f32 %0, %1, %2;" : "=r"(l) : "f"(y - hy), "f"(x - hx));
}

__device__ __forceinline__ void cp16(uint32_t saddr, const void* gptr) {
    asm volatile("cp.async.cg.shared.global [%0], [%1], 16;"
                 :: "r"(saddr), "l"(gptr) : "memory");
}
#define CP_COMMIT() asm volatile("cp.async.commit_group;" ::: "memory")
template<int N>
__device__ __forceinline__ void cp_wait() {
    asm volatile("cp.async.wait_group %0;" :: "n"(N) : "memory");
}

__global__ __launch_bounds__(256)
void cvt_split(const float* __restrict__ src,
               uint32_t* __restrict__ hi, uint32_t* __restrict__ lo, int n2) {
    int i = blockIdx.x * blockDim.x + threadIdx.x;
    if (i >= n2) return;
    float2 v = ((const float2*)src)[i];
    uint32_t h, l;
    split2(v.x, v.y, h, l);
    hi[i] = h;
    lo[i] = l;
}

// V^T split: out [b*NH+h][d][SEQ/2 pairs], pairs packed along key (token)
__global__ __launch_bounds__(256)
void cvt_vT() {
    __shared__ float tile[32][65];
    const int bh = blockIdx.y;
    const int b  = bh >> 4, h = bh & 15;
    const int t0 = blockIdx.x * 32;
    const int tid = threadIdx.x;
#pragma unroll
    for (int r = 0; r < 8; r++) {
        int e  = r * 256 + tid;
        int ti = e >> 6, d = e & 63;
        tile[ti][d] = g_qkv[(size_t)(b * SEQ + t0 + ti) * QKVD + 2 * DIMX + h * HD + d];
    }
    __syncthreads();
    const int d  = tid >> 2;
    const int pg = (tid & 3) * 4;
    size_t obase = ((size_t)bh * HD + d) * (SEQ / 2) + (t0 >> 1) + pg;
#pragma unroll
    for (int p = 0; p < 4; p++) {
        uint32_t hh, ll;
        split2(tile[2 * (pg + p)][d], tile[2 * (pg + p) + 1][d], hh, ll);
        g_vth[obase + p] = hh;
        g_vtl[obase + p] = ll;
    }
}

// mma.sync m16n8k16 bf16 (row.col), fp32 accumulate
__device__ __forceinline__ void mma_bf16(float* d, const uint32_t* a, const uint32_t* b) {
    asm volatile(
        "mma.sync.aligned.m16n8k16.row.col.f32.bf16.bf16.f32 "
        "{%0,%1,%2,%3}, {%4,%5,%6,%7}, {%8,%9}, {%0,%1,%2,%3};"
        : "+f"(d[0]), "+f"(d[1]), "+f"(d[2]), "+f"(d[3])
        : "r"(a[0]), "r"(a[1]), "r"(a[2]), "r"(a[3]), "r"(b[0]), "r"(b[1]));
}

__device__ __forceinline__ void ldsm4(uint32_t* r, uint32_t addr) {
    asm volatile("ldmatrix.sync.aligned.m8n8.x4.shared.b16 {%0,%1,%2,%3}, [%4];"
                 : "=r"(r[0]), "=r"(r[1]), "=r"(r[2]), "=r"(r[3]) : "r"(addr));
}

// ---------------------------------------------------------------------------
// 3-term bf16 NT GEMM: ldmatrix + 3-stage cp.async, k-chunk = 32 values.
// C[M,N] = A[M,K] * B[N,K]^T. CTA 128x128, 256 thr (8 warps 2x4), warp 64x32.
// Tile layout: [128 rows][16 u32]; 16B chunk swizzle c' = c ^ ((row>>1)&3)
// (8-row ldmatrix at fixed chunk -> 8 distinct 16B bank groups).
// Stage = 4 tiles x 8KB = 32KB; 3 stages = 96KB dynamic smem, 2 CTA/SM.
// MODE 0: fp32 C.  MODE 1: split epilogue for qkv (Q scaled; fp32 V third).
// ---------------------------------------------------------------------------
#define TW     16                    // u32 per tile row
#define TILE   (128 * TW)            // 2048 u32
#define P_AH   0
#define P_AL   TILE
#define P_BH   (2 * TILE)
#define P_BL   (3 * TILE)
#define STGU   (4 * TILE)            // 8192 u32 per stage
#define NSTAGE 3
#define GT_SMEM (NSTAGE * STGU * 4)  // 98304 B

template<int MODE>
__global__ __launch_bounds__(256, 2)
void gemm_bf3(const uint32_t* __restrict__ Ah_, const uint32_t* __restrict__ Al_,
              const uint32_t* __restrict__ Bh_, const uint32_t* __restrict__ Bl_,
              float* __restrict__ C, int M, int N, int K) {
    extern __shared__ uint32_t smbuf[];

    const int tid   = threadIdx.x;
    const int lane  = tid & 31;
    const int wid   = tid >> 5;
    const int warpm = wid >> 2;
    const int warpn = wid & 3;
    const int g     = lane >> 2;
    const int tg    = lane & 3;
    const int bm    = blockIdx.y << 7;
    const int bn    = blockIdx.x << 7;
    const int KP    = K >> 1;

    // staging: thread = (row, 2 chunks of 16B); swizzled chunk
    const int srow  = tid >> 1;
    const int shalf = tid & 1;
    const int ssw   = (srow >> 1) & 3;
    const uint32_t st0 = (uint32_t)srow * TW + 4 * ((2 * shalf + 0) ^ ssw);
    const uint32_t st1 = (uint32_t)srow * TW + 4 * ((2 * shalf + 1) ^ ssw);

    // ldmatrix lane addressing
    const int rA   = warpm * 64 + (lane & 15);
    const int cA   = lane >> 4;                  // 0/1: 16B half of a k-step
    const int swzA = (rA >> 1) & 3;
    const int rB   = warpn * 32 + (lane & 7) + ((lane >> 4) << 3);
    const int cB   = (lane >> 3) & 1;
    const int swzB = (rB >> 1) & 3;

    const uint32_t sb = smem_u32(smbuf);

    const uint32_t* pAh = Ah_ + (size_t)(bm + srow) * KP + (2 * shalf) * 4;
    const uint32_t* pAl = Al_ + (size_t)(bm + srow) * KP + (2 * shalf) * 4;
    const uint32_t* pBh = Bh_ + (size_t)(bn + srow) * KP + (2 * shalf) * 4;
    const uint32_t* pBl = Bl_ + (size_t)(bn + srow) * KP + (2 * shalf) * 4;

    float acc[4][4][4];
#pragma unroll
    for (int i = 0; i < 4; i++)
#pragma unroll
        for (int j = 0; j < 4; j++)
#pragma unroll
            for (int q = 0; q < 4; q++) acc[i][j][q] = 0.f;

    const int nt = K >> 5;               // chunks of 32 k-values (16 u32)

    // prologue: issue chunks 0 and 1
#pragma unroll
    for (int p = 0; p < 2; p++) {
        uint32_t dstb = sb + p * (STGU * 4);
        cp16(dstb + (P_AH + st0) * 4, pAh + (size_t)p * 16);
        cp16(dstb + (P_AH + st1) * 4, pAh + (size_t)p * 16 + 4);
        cp16(dstb + (P_AL + st0) * 4, pAl + (size_t)p * 16);
        cp16(dstb + (P_AL + st1) * 4, pAl + (size_t)p * 16 + 4);
        cp16(dstb + (P_BH + st0) * 4, pBh + (size_t)p * 16);
        cp16(dstb + (P_BH + st1) * 4, pBh + (size_t)p * 16 + 4);
        cp16(dstb + (P_BL + st0) * 4, pBl + (size_t)p * 16);
        cp16(dstb + (P_BL + st1) * 4, pBl + (size_t)p * 16 + 4);
        CP_COMMIT();
    }

    int stage = 0;
    for (int t = 0; t < nt; t++) {
        cp_wait<1>();
        __syncthreads();

        if (t + 2 < nt) {
            uint32_t dstb = sb + ((stage + 2 >= NSTAGE) ? (stage + 2 - NSTAGE) : (stage + 2)) * (STGU * 4);
            cp16(dstb + (P_AH + st0) * 4, pAh + (size_t)(t + 2) * 16);
            cp16(dstb + (P_AH + st1) * 4, pAh + (size_t)(t + 2) * 16 + 4);
            cp16(dstb + (P_AL + st0) * 4, pAl + (size_t)(t + 2) * 16);
            cp16(dstb + (P_AL + st1) * 4, pAl + (size_t)(t + 2) * 16 + 4);
            cp16(dstb + (P_BH + st0) * 4, pBh + (size_t)(t + 2) * 16);
            cp16(dstb + (P_BH + st1) * 4, pBh + (size_t)(t + 2) * 16 + 4);
            cp16(dstb + (P_BL + st0) * 4, pBl + (size_t)(t + 2) * 16);
            cp16(dstb + (P_BL + st1) * 4, pBl + (size_t)(t + 2) * 16 + 4);
            CP_COMMIT();
        }

        const uint32_t base = sb + stage * (STGU * 4);

#pragma unroll
        for (int ks = 0; ks < 2; ks++) {
            const uint32_t aoff = (uint32_t)rA * 64 + 16 * ((2 * ks + cA) ^ swzA);
            const uint32_t boff = (uint32_t)rB * 64 + 16 * ((2 * ks + cB) ^ swzB);

            uint32_t bh0[4], bh1[4], bl0[4], bl1[4];
            ldsm4(bh0, base + P_BH * 4 + boff);
            ldsm4(bh1, base + P_BH * 4 + boff + 1024);
            ldsm4(bl0, base + P_BL * 4 + boff);
            ldsm4(bl1, base + P_BL * 4 + boff + 1024);

#pragma unroll
            for (int i = 0; i < 4; i++) {
                uint32_t ah[4], al[4];
                ldsm4(ah, base + P_AH * 4 + aoff + i * 1024);
                ldsm4(al, base + P_AL * 4 + aoff + i * 1024);
                mma_bf16(acc[i][0], ah, &bh0[0]);
                mma_bf16(acc[i][1], ah, &bh0[2]);
                mma_bf16(acc[i][2], ah, &bh1[0]);
                mma_bf16(acc[i][3], ah, &bh1[2]);
                mma_bf16(acc[i][0], ah, &bl0[0]);
                mma_bf16(acc[i][1], ah, &bl0[2]);
                mma_bf16(acc[i][2], ah, &bl1[0]);
                mma_bf16(acc[i][3], ah, &bl1[2]);
                mma_bf16(acc[i][0], al, &bh0[0]);
                mma_bf16(acc[i][1], al, &bh0[2]);
                mma_bf16(acc[i][2], al, &bh1[0]);
                mma_bf16(acc[i][3], al, &bh1[2]);
            }
        }

        stage = (stage + 1 == NSTAGE) ? 0 : stage + 1;
    }

    if (MODE == 0) {
#pragma unroll
        for (int i = 0; i < 4; i++) {
            int row = bm + warpm * 64 + i * 16 + g;
#pragma unroll
            for (int j = 0; j < 4; j++) {
                int col = bn + warpn * 32 + j * 8 + 2 * tg;
                *(float2*)&C[(size_t)row * N + col]       = make_float2(acc[i][j][0], acc[i][j][1]);
                *(float2*)&C[(size_t)(row + 8) * N + col] = make_float2(acc[i][j][2], acc[i][j][3]);
            }
        }
    } else {
        const float sc = (bn < 1024) ? 0.125f : 1.0f;   // Q pre-scale (exact, pow2)
        const bool  wv = (bn >= 2048);                  // V third -> fp32 for cvt_vT
#pragma unroll
        for (int i = 0; i < 4; i++) {
            int row = bm + warpm * 64 + i * 16 + g;
#pragma unroll
            for (int j = 0; j < 4; j++) {
                int col  = bn + warpn * 32 + j * 8 + 2 * tg;
                int colp = col >> 1;
                uint32_t h0, l0, h1, l1;
                split2(acc[i][j][0] * sc, acc[i][j][1] * sc, h0, l0);
                split2(acc[i][j][2] * sc, acc[i][j][3] * sc, h1, l1);
                g_qkvh[(size_t)row * KQ + colp]       = h0;
                g_qkvl[(size_t)row * KQ + colp]       = l0;
                g_qkvh[(size_t)(row + 8) * KQ + colp] = h1;
                g_qkvl[(size_t)(row + 8) * KQ + colp] = l1;
                if (wv) {
                    *(float2*)&g_qkv[(size_t)row * QKVD + col]       = make_float2(acc[i][j][0], acc[i][j][1]);
                    *(float2*)&g_qkv[(size_t)(row + 8) * QKVD + col] = make_float2(acc[i][j][2], acc[i][j][3]);
                }
            }
        }
    }
}

// ---------------------------------------------------------------------------
// Causal flash attention, mma.sync, operands pre-split in gmem.
// (unchanged from R15)
// ---------------------------------------------------------------------------
#define AT_SMEM (12800 * 4)

__global__ __launch_bounds__(128, 3)
void attn_mma() {
    extern __shared__ uint32_t sm[];
    uint32_t* Qh = sm;
    uint32_t* Ql = sm + 2048;
    uint32_t* Kh = sm + 4096;
    uint32_t* Kl = sm + 6144;
    uint32_t* Vh = sm + 8192;
    uint32_t* Vl = sm + 10496;

    const int tid  = threadIdx.x;
    const int lane = tid & 31;
    const int wid  = tid >> 5;
    const int g    = lane >> 2;
    const int tg   = lane & 3;
    const int rb   = wid << 4;
    const int qb   = blockIdx.x;
    const int h    = blockIdx.y;
    const int b    = blockIdx.z;

    const int srow = tid >> 1;
    const int shf  = tid & 1;
    const int s    = srow & 7;
    const uint32_t sb = smem_u32(sm);

    // ---- stage Q (pre-scaled hi/lo from gmem) ----
    {
        size_t base = (size_t)(b * SEQ + qb * 64 + srow) * KQ + h * 32 + shf * 16;
#pragma unroll
        for (int i = 0; i < 4; i++) {
            uint4 vh4 = *(const uint4*)(g_qkvh + base + i * 4);
            uint4 vl4 = *(const uint4*)(g_qkvl + base + i * 4);
            int p0 = shf * 16 + i * 4;
            int sbase = ((p0 >> 3) * 64 + srow) * 8;
            int kp = p0 & 7;
            Qh[sbase + ((kp + 0) ^ s)] = vh4.x;
            Qh[sbase + ((kp + 1) ^ s)] = vh4.y;
            Qh[sbase + ((kp + 2) ^ s)] = vh4.z;
            Qh[sbase + ((kp + 3) ^ s)] = vh4.w;
            Ql[sbase + ((kp + 0) ^ s)] = vl4.x;
            Ql[sbase + ((kp + 1) ^ s)] = vl4.y;
            Ql[sbase + ((kp + 2) ^ s)] = vl4.z;
            Ql[sbase + ((kp + 3) ^ s)] = vl4.w;
        }
    }

    float m0 = -1e30f, m1 = -1e30f, l0s = 0.f, l1s = 0.f;
    float oacc[8][4];
#pragma unroll
    for (int j = 0; j < 8; j++)
#pragma unroll
        for (int q = 0; q < 4; q++) oacc[j][q] = 0.f;

    const int c0 = tg ^ g;
    const int c1 = (tg + 4) ^ g;

    for (int kb = 0; kb <= qb; kb++) {
        __syncthreads();

        // ---- V^T hi/lo via cp.async (linear layout, overlaps K staging) ----
        {
            size_t vbase = ((size_t)(b * NH + h) * HD + srow) * (SEQ / 2) + kb * 32 + shf * 16;
            const int d36 = srow * 36 + shf * 16;
            uint32_t vdstH = sb + (8192 + d36) * 4;
            uint32_t vdstL = sb + (10496 + d36) * 4;
#pragma unroll
            for (int i = 0; i < 4; i++) {
                cp16(vdstH + i * 16, g_vth + vbase + i * 4);
                cp16(vdstL + i * 16, g_vtl + vbase + i * 4);
            }
            CP_COMMIT();
        }

        // ---- stage K hi/lo (scalar scatter, swizzled) ----
        {
            size_t base = (size_t)(b * SEQ + kb * 64 + srow) * KQ + 512 + h * 32 + shf * 16;
#pragma unroll
            for (int i = 0; i < 4; i++) {
                uint4 vh4 = *(const uint4*)(g_qkvh + base + i * 4);
                uint4 vl4 = *(const uint4*)(g_qkvl + base + i * 4);
                int p0 = shf * 16 + i * 4;
                int sbase = ((p0 >> 3) * 64 + srow) * 8;
                int kp = p0 & 7;
                Kh[sbase + ((kp + 0) ^ s)] = vh4.x;
                Kh[sbase + ((kp + 1) ^ s)] = vh4.y;
                Kh[sbase + ((kp + 2) ^ s)] = vh4.z;
                Kh[sbase + ((kp + 3) ^ s)] = vh4.w;
                Kl[sbase + ((kp + 0) ^ s)] = vl4.x;
                Kl[sbase + ((kp + 1) ^ s)] = vl4.y;
                Kl[sbase + ((kp + 2) ^ s)] = vl4.z;
                Kl[sbase + ((kp + 3) ^ s)] = vl4.w;
            }
        }
        cp_wait<0>();
        __syncthreads();

        // ---- S = Q K^T, 3-term ----
        float sacc[8][4];
#pragma unroll
        for (int j = 0; j < 8; j++)
#pragma unroll
            for (int q = 0; q < 4; q++) sacc[j][q] = 0.f;

#pragma unroll
        for (int c = 0; c < 4; c++) {
            uint32_t a[4], bb[8][2];
            const int ab  = c * 512 + (rb + g) * 8;
            const int ab8 = c * 512 + (rb + g + 8) * 8;
            a[0] = Qh[ab + c0];  a[1] = Qh[ab8 + c0];
            a[2] = Qh[ab + c1];  a[3] = Qh[ab8 + c1];
#pragma unroll
            for (int j = 0; j < 8; j++) {
                int nb = c * 512 + (j * 8 + g) * 8;
                bb[j][0] = Kh[nb + c0];
                bb[j][1] = Kh[nb + c1];
            }
#pragma unroll
            for (int j = 0; j < 8; j++) mma_bf16(sacc[j], a, bb[j]);
#pragma unroll
            for (int j = 0; j < 8; j++) {
                int nb = c * 512 + (j * 8 + g) * 8;
                bb[j][0] = Kl[nb + c0];
                bb[j][1] = Kl[nb + c1];
            }
#pragma unroll
            for (int j = 0; j < 8; j++) mma_bf16(sacc[j], a, bb[j]);
            a[0] = Ql[ab + c0];  a[1] = Ql[ab8 + c0];
            a[2] = Ql[ab + c1];  a[3] = Ql[ab8 + c1];
#pragma unroll
            for (int j = 0; j < 8; j++) {
                int nb = c * 512 + (j * 8 + g) * 8;
                bb[j][0] = Kh[nb + c0];
                bb[j][1] = Kh[nb + c1];
            }
#pragma unroll
            for (int j = 0; j < 8; j++) mma_bf16(sacc[j], a, bb[j]);
        }

        // ---- causal mask on diagonal block ----
        if (kb == qb) {
            const int r0 = rb + g, r1 = rb + g + 8;
#pragma unroll
            for (int j = 0; j < 8; j++) {
                int col = j * 8 + 2 * tg;
                if (col     > r0) sacc[j][0] = -1e30f;
                if (col + 1 > r0) sacc[j][1] = -1e30f;
                if (col     > r1) sacc[j][2] = -1e30f;
                if (col + 1 > r1) sacc[j][3] = -1e30f;
            }
        }

        // ---- online softmax ----
        float mx0 = -1e30f, mx1 = -1e30f;
#pragma unroll
        for (int j = 0; j < 8; j++) {
            mx0 = fmaxf(mx0, fmaxf(sacc[j][0], sacc[j][1]));
            mx1 = fmaxf(mx1, fmaxf(sacc[j][2], sacc[j][3]));
        }
        mx0 = fmaxf(mx0, __shfl_xor_sync(0xffffffffu, mx0, 1));
        mx0 = fmaxf(mx0, __shfl_xor_sync(0xffffffffu, mx0, 2));
        mx1 = fmaxf(mx1, __shfl_xor_sync(0xffffffffu, mx1, 1));
        mx1 = fmaxf(mx1, __shfl_xor_sync(0xffffffffu, mx1, 2));

        float mn0 = fmaxf(m0, mx0), mn1 = fmaxf(m1, mx1);
        float al0 = __expf(m0 - mn0), al1 = __expf(m1 - mn1);
        m0 = mn0; m1 = mn1;

        float rs0 = 0.f, rs1 = 0.f;
#pragma unroll
        for (int j = 0; j < 8; j++) {
            sacc[j][0] = __expf(sacc[j][0] - mn0); rs0 += sacc[j][0];
            sacc[j][1] = __expf(sacc[j][1] - mn0); rs0 += sacc[j][1];
            sacc[j][2] = __expf(sacc[j][2] - mn1); rs1 += sacc[j][2];
            sacc[j][3] = __expf(sacc[j][3] - mn1); rs1 += sacc[j][3];
        }
        rs0 += __shfl_xor_sync(0xffffffffu, rs0, 1);
        rs0 += __shfl_xor_sync(0xffffffffu, rs0, 2);
        rs1 += __shfl_xor_sync(0xffffffffu, rs1, 1);
        rs1 += __shfl_xor_sync(0xffffffffu, rs1, 2);
        l0s = l0s * al0 + rs0;
        l1s = l1s * al1 + rs1;

#pragma unroll
        for (int j = 0; j < 8; j++) {
            oacc[j][0] *= al0; oacc[j][1] *= al0;
            oacc[j][2] *= al1; oacc[j][3] *= al1;
        }

        // ---- O += P V, 3-term ----
#pragma unroll
        for (int cc = 0; cc < 4; cc++) {
            uint32_t ph[4], pl[4];
            split2(sacc[2 * cc][0],     sacc[2 * cc][1],     ph[0], pl[0]);
            split2(sacc[2 * cc][2],     sacc[2 * cc][3],     ph[1], pl[1]);
            split2(sacc[2 * cc + 1][0], sacc[2 * cc + 1][1], ph[2], pl[2]);
            split2(sacc[2 * cc + 1][2], sacc[2 * cc + 1][3], ph[3], pl[3]);
#pragma unroll
            for (int j2 = 0; j2 < 8; j2++) {
                int vo = (j2 * 8 + g) * 36 + cc * 8 + tg;
                uint32_t vh2[2] = { Vh[vo], Vh[vo + 4] };
                uint32_t vl2[2] = { Vl[vo], Vl[vo + 4] };
                mma_bf16(oacc[j2], ph, vh2);
                mma_bf16(oacc[j2], pl, vh2);
                mma_bf16(oacc[j2], ph, vl2);
            }
        }
    }

    // ---- finalize: write hi/lo bf16x2 directly for GEMM2 ----
    const float inv0 = 1.0f / l0s, inv1 = 1.0f / l1s;
    const size_t row0 = (size_t)(b * SEQ + qb * 64 + rb + g);
#pragma unroll
    for (int j2 = 0; j2 < 8; j2++) {
        uint32_t h0, l0, h1, l1;
        split2(oacc[j2][0] * inv0, oacc[j2][1] * inv0, h0, l0);
        split2(oacc[j2][2] * inv1, oacc[j2][3] * inv1, h1, l1);
        size_t idx0 = row0 * KH + h * 32 + j2 * 4 + tg;
        g_ah[idx0]            = h0;
        g_al[idx0]            = l0;
        g_ah[idx0 + 8 * KH]   = h1;
        g_al[idx0 + 8 * KH]   = l1;
    }
}

// ---------------------------------------------------------------------------
// launch
// ---------------------------------------------------------------------------
extern "C" void kernel_launch(void* const* d_in, const int* in_sizes, int n_in,
                              void* d_out, int out_size) {
    const float* x    = (const float*)d_in[0];   // [4,2048,1024]
    const float* Wqkv = (const float*)d_in[1];   // [3072,1024]
    const float* Wout = (const float*)d_in[2];   // [1024,1024]
    float*       out  = (float*)d_out;           // [4,2048,1024]

    uint32_t *xh, *xl, *wqh, *wql, *woh, *wol, *ah, *al;
    cudaGetSymbolAddress((void**)&xh,  g_xh);
    cudaGetSymbolAddress((void**)&xl,  g_xl);
    cudaGetSymbolAddress((void**)&wqh, g_wqh);
    cudaGetSymbolAddress((void**)&wql, g_wql);
    cudaGetSymbolAddress((void**)&woh, g_woh);
    cudaGetSymbolAddress((void**)&wol, g_wol);
    cudaGetSymbolAddress((void**)&ah,  g_ah);
    cudaGetSymbolAddress((void**)&al,  g_al);

    cudaFuncSetAttribute(gemm_bf3<0>, cudaFuncAttributeMaxDynamicSharedMemorySize, GT_SMEM);
    cudaFuncSetAttribute(gemm_bf3<1>, cudaFuncAttributeMaxDynamicSharedMemorySize, GT_SMEM);
    cudaFuncSetAttribute(attn_mma,    cudaFuncAttributeMaxDynamicSharedMemorySize, AT_SMEM);

    // 0) split inputs
    const int n2x = ROWS * KH;
    const int n2q = QKVD * KH;
    const int n2o = DIMX * KH;
    cvt_split<<<n2x / 256, 256>>>(x,    xh,  xl,  n2x);
    cvt_split<<<n2q / 256, 256>>>(Wqkv, wqh, wql, n2q);
    cvt_split<<<n2o / 256, 256>>>(Wout, woh, wol, n2o);

    // 1) qkv = x @ Wqkv^T — fused epilogue writes split hi/lo (+ fp32 V third)
    dim3 g1(QKVD / 128, ROWS / 128);
    gemm_bf3<1><<<g1, 256, GT_SMEM>>>(xh, xl, wqh, wql, nullptr, ROWS, QKVD, DIMX);

    // 1b) build transposed V hi/lo
    dim3 gv(SEQ / 32, BATCH * NH);
    cvt_vT<<<gv, 256>>>();

    // 2) causal attention -> g_ah/g_al (bf16x2 hi/lo)
    dim3 g2(SEQ / 64, NH, BATCH);
    attn_mma<<<g2, 128, AT_SMEM>>>();

    // 3) out = att @ Wout^T [8192,1024]
    dim3 g3(DIMX / 128, ROWS / 128);
    gemm_bf3<0><<<g3, 256, GT_SMEM>>>(ah, al, woh, wol, out, ROWS, DIMX, DIMX);
}

// round 17
// speedup vs baseline: 1.1023x; 1.1023x over previous
#include <cuda_runtime.h>
#include <cstdint>

// ---------------------------------------------------------------------------
// Problem constants
// ---------------------------------------------------------------------------
#define DIMX   1024
#define NH     16
#define HD     64
#define BATCH  4
#define SEQ    2048
#define ROWS   (BATCH * SEQ)        // 8192
#define QKVD   (3 * DIMX)           // 3072
#define KH     (DIMX / 2)           // 512 u32 pairs per 1024 cols
#define KQ     (QKVD / 2)           // 1536 u32 pairs per qkv row

// ---------------------------------------------------------------------------
// Scratch (__device__ globals; allocation is forbidden)
// ---------------------------------------------------------------------------
__device__ float    g_qkv [(size_t)ROWS * QKVD];   // fp32 qkv (V section only)
__device__ uint32_t g_qkvh[(size_t)ROWS * KQ];     // qkv hi (Q pre-scaled)
__device__ uint32_t g_qkvl[(size_t)ROWS * KQ];     // qkv lo
__device__ uint32_t g_vth [(size_t)BATCH * NH * HD * (SEQ / 2)];  // V^T hi
__device__ uint32_t g_vtl [(size_t)BATCH * NH * HD * (SEQ / 2)];  // V^T lo
__device__ uint32_t g_xh  [(size_t)ROWS * KH];
__device__ uint32_t g_xl  [(size_t)ROWS * KH];
__device__ uint32_t g_wqh [(size_t)QKVD * KH];
__device__ uint32_t g_wql [(size_t)QKVD * KH];
__device__ uint32_t g_woh [(size_t)DIMX * KH];
__device__ uint32_t g_wol [(size_t)DIMX * KH];
__device__ uint32_t g_ah  [(size_t)ROWS * KH];     // attention out hi
__device__ uint32_t g_al  [(size_t)ROWS * KH];     // attention out lo

// ---------------------------------------------------------------------------
// helpers
// ---------------------------------------------------------------------------
__device__ __forceinline__ uint32_t smem_u32(const void* p) {
    uint32_t a;
    asm("{ .reg .u64 t; cvta.to.shared.u64 t, %1; cvt.u32.u64 %0, t; }"
        : "=r"(a) : "l"(p));
    return a;
}

__device__ __forceinline__ void split2(float x, float y, uint32_t& h, uint32_t& l) {
    asm("cvt.rn.bf16x2.f32 %0, %1, %2;" : "=r"(h) : "f"(y), "f"(x));
    float hx = __uint_as_float(h << 16);
    float hy = __uint_as_float(h & 0xFFFF0000u);
    asm("cvt.rn.bf16x2.f32 %0, %1, %2;" : "=r"(l) : "f"(y - hy), "f"(x - hx));
}

__device__ __forceinline__ void cp16(uint32_t saddr, const void* gptr) {
    asm volatile("cp.async.cg.shared.global [%0], [%1], 16;"
                 :: "r"(saddr), "l"(gptr) : "memory");
}
#define CP_COMMIT() asm volatile("cp.async.commit_group;" ::: "memory")
template<int N>
__device__ __forceinline__ void cp_wait() {
    asm volatile("cp.async.wait_group %0;" :: "n"(N) : "memory");
}

__global__ __launch_bounds__(256)
void cvt_split(const float* __restrict__ src,
               uint32_t* __restrict__ hi, uint32_t* __restrict__ lo, int n2) {
    int i = blockIdx.x * blockDim.x + threadIdx.x;
    if (i >= n2) return;
    float2 v = ((const float2*)src)[i];
    uint32_t h, l;
    split2(v.x, v.y, h, l);
    hi[i] = h;
    lo[i] = l;
}

// V^T split: out [b*NH+h][d][SEQ/2 pairs], pairs packed along key (token)
__global__ __launch_bounds__(256)
void cvt_vT() {
    __shared__ float tile[32][65];
    const int bh = blockIdx.y;
    const int b  = bh >> 4, h = bh & 15;
    const int t0 = blockIdx.x * 32;
    const int tid = threadIdx.x;
#pragma unroll
    for (int r = 0; r < 8; r++) {
        int e  = r * 256 + tid;
        int ti = e >> 6, d = e & 63;
        tile[ti][d] = g_qkv[(size_t)(b * SEQ + t0 + ti) * QKVD + 2 * DIMX + h * HD + d];
    }
    __syncthreads();
    const int d  = tid >> 2;
    const int pg = (tid & 3) * 4;
    size_t obase = ((size_t)bh * HD + d) * (SEQ / 2) + (t0 >> 1) + pg;
#pragma unroll
    for (int p = 0; p < 4; p++) {
        uint32_t hh, ll;
        split2(tile[2 * (pg + p)][d], tile[2 * (pg + p) + 1][d], hh, ll);
        g_vth[obase + p] = hh;
        g_vtl[obase + p] = ll;
    }
}

// mma.sync m16n8k16 bf16 (row.col), fp32 accumulate
__device__ __forceinline__ void mma_bf16(float* d, const uint32_t* a, const uint32_t* b) {
    asm volatile(
        "mma.sync.aligned.m16n8k16.row.col.f32.bf16.bf16.f32 "
        "{%0,%1,%2,%3}, {%4,%5,%6,%7}, {%8,%9}, {%0,%1,%2,%3};"
        : "+f"(d[0]), "+f"(d[1]), "+f"(d[2]), "+f"(d[3])
        : "r"(a[0]), "r"(a[1]), "r"(a[2]), "r"(a[3]), "r"(b[0]), "r"(b[1]));
}

__device__ __forceinline__ void ldsm4(uint32_t* r, uint32_t addr) {
    asm volatile("ldmatrix.sync.aligned.m8n8.x4.shared.b16 {%0,%1,%2,%3}, [%4];"
                 : "=r"(r[0]), "=r"(r[1]), "=r"(r[2]), "=r"(r[3]) : "r"(addr));
}

// ---------------------------------------------------------------------------
// 3-term bf16 NT GEMM: ldmatrix + 3-stage cp.async, k-chunk = 32 values.
// (unchanged from R16)
// ---------------------------------------------------------------------------
#define TW     16
#define TILE   (128 * TW)
#define P_AH   0
#define P_AL   TILE
#define P_BH   (2 * TILE)
#define P_BL   (3 * TILE)
#define STGU   (4 * TILE)
#define NSTAGE 3
#define GT_SMEM (NSTAGE * STGU * 4)

template<int MODE>
__global__ __launch_bounds__(256, 2)
void gemm_bf3(const uint32_t* __restrict__ Ah_, const uint32_t* __restrict__ Al_,
              const uint32_t* __restrict__ Bh_, const uint32_t* __restrict__ Bl_,
              float* __restrict__ C, int M, int N, int K) {
    extern __shared__ uint32_t smbuf[];

    const int tid   = threadIdx.x;
    const int lane  = tid & 31;
    const int wid   = tid >> 5;
    const int warpm = wid >> 2;
    const int warpn = wid & 3;
    const int g     = lane >> 2;
    const int tg    = lane & 3;
    const int bm    = blockIdx.y << 7;
    const int bn    = blockIdx.x << 7;
    const int KP    = K >> 1;

    const int srow  = tid >> 1;
    const int shalf = tid & 1;
    const int ssw   = (srow >> 1) & 3;
    const uint32_t st0 = (uint32_t)srow * TW + 4 * ((2 * shalf + 0) ^ ssw);
    const uint32_t st1 = (uint32_t)srow * TW + 4 * ((2 * shalf + 1) ^ ssw);

    const int rA   = warpm * 64 + (lane & 15);
    const int cA   = lane >> 4;
    const int swzA = (rA >> 1) & 3;
    const int rB   = warpn * 32 + (lane & 7) + ((lane >> 4) << 3);
    const int cB   = (lane >> 3) & 1;
    const int swzB = (rB >> 1) & 3;

    const uint32_t sb = smem_u32(smbuf);

    const uint32_t* pAh = Ah_ + (size_t)(bm + srow) * KP + (2 * shalf) * 4;
    const uint32_t* pAl = Al_ + (size_t)(bm + srow) * KP + (2 * shalf) * 4;
    const uint32_t* pBh = Bh_ + (size_t)(bn + srow) * KP + (2 * shalf) * 4;
    const uint32_t* pBl = Bl_ + (size_t)(bn + srow) * KP + (2 * shalf) * 4;

    float acc[4][4][4];
#pragma unroll
    for (int i = 0; i < 4; i++)
#pragma unroll
        for (int j = 0; j < 4; j++)
#pragma unroll
            for (int q = 0; q < 4; q++) acc[i][j][q] = 0.f;

    const int nt = K >> 5;

#pragma unroll
    for (int p = 0; p < 2; p++) {
        uint32_t dstb = sb + p * (STGU * 4);
        cp16(dstb + (P_AH + st0) * 4, pAh + (size_t)p * 16);
        cp16(dstb + (P_AH + st1) * 4, pAh + (size_t)p * 16 + 4);
        cp16(dstb + (P_AL + st0) * 4, pAl + (size_t)p * 16);
        cp16(dstb + (P_AL + st1) * 4, pAl + (size_t)p * 16 + 4);
        cp16(dstb + (P_BH + st0) * 4, pBh + (size_t)p * 16);
        cp16(dstb + (P_BH + st1) * 4, pBh + (size_t)p * 16 + 4);
        cp16(dstb + (P_BL + st0) * 4, pBl + (size_t)p * 16);
        cp16(dstb + (P_BL + st1) * 4, pBl + (size_t)p * 16 + 4);
        CP_COMMIT();
    }

    int stage = 0;
    for (int t = 0; t < nt; t++) {
        cp_wait<1>();
        __syncthreads();

        if (t + 2 < nt) {
            uint32_t dstb = sb + ((stage + 2 >= NSTAGE) ? (stage + 2 - NSTAGE) : (stage + 2)) * (STGU * 4);
            cp16(dstb + (P_AH + st0) * 4, pAh + (size_t)(t + 2) * 16);
            cp16(dstb + (P_AH + st1) * 4, pAh + (size_t)(t + 2) * 16 + 4);
            cp16(dstb + (P_AL + st0) * 4, pAl + (size_t)(t + 2) * 16);
            cp16(dstb + (P_AL + st1) * 4, pAl + (size_t)(t + 2) * 16 + 4);
            cp16(dstb + (P_BH + st0) * 4, pBh + (size_t)(t + 2) * 16);
            cp16(dstb + (P_BH + st1) * 4, pBh + (size_t)(t + 2) * 16 + 4);
            cp16(dstb + (P_BL + st0) * 4, pBl + (size_t)(t + 2) * 16);
            cp16(dstb + (P_BL + st1) * 4, pBl + (size_t)(t + 2) * 16 + 4);
            CP_COMMIT();
        }

        const uint32_t base = sb + stage * (STGU * 4);

#pragma unroll
        for (int ks = 0; ks < 2; ks++) {
            const uint32_t aoff = (uint32_t)rA * 64 + 16 * ((2 * ks + cA) ^ swzA);
            const uint32_t boff = (uint32_t)rB * 64 + 16 * ((2 * ks + cB) ^ swzB);

            uint32_t bh0[4], bh1[4], bl0[4], bl1[4];
            ldsm4(bh0, base + P_BH * 4 + boff);
            ldsm4(bh1, base + P_BH * 4 + boff + 1024);
            ldsm4(bl0, base + P_BL * 4 + boff);
            ldsm4(bl1, base + P_BL * 4 + boff + 1024);

#pragma unroll
            for (int i = 0; i < 4; i++) {
                uint32_t ah[4], al[4];
                ldsm4(ah, base + P_AH * 4 + aoff + i * 1024);
                ldsm4(al, base + P_AL * 4 + aoff + i * 1024);
                mma_bf16(acc[i][0], ah, &bh0[0]);
                mma_bf16(acc[i][1], ah, &bh0[2]);
                mma_bf16(acc[i][2], ah, &bh1[0]);
                mma_bf16(acc[i][3], ah, &bh1[2]);
                mma_bf16(acc[i][0], ah, &bl0[0]);
                mma_bf16(acc[i][1], ah, &bl0[2]);
                mma_bf16(acc[i][2], ah, &bl1[0]);
                mma_bf16(acc[i][3], ah, &bl1[2]);
                mma_bf16(acc[i][0], al, &bh0[0]);
                mma_bf16(acc[i][1], al, &bh0[2]);
                mma_bf16(acc[i][2], al, &bh1[0]);
                mma_bf16(acc[i][3], al, &bh1[2]);
            }
        }

        stage = (stage + 1 == NSTAGE) ? 0 : stage + 1;
    }

    if (MODE == 0) {
#pragma unroll
        for (int i = 0; i < 4; i++) {
            int row = bm + warpm * 64 + i * 16 + g;
#pragma unroll
            for (int j = 0; j < 4; j++) {
                int col = bn + warpn * 32 + j * 8 + 2 * tg;
                *(float2*)&C[(size_t)row * N + col]       = make_float2(acc[i][j][0], acc[i][j][1]);
                *(float2*)&C[(size_t)(row + 8) * N + col] = make_float2(acc[i][j][2], acc[i][j][3]);
            }
        }
    } else {
        const float sc = (bn < 1024) ? 0.125f : 1.0f;
        const bool  wv = (bn >= 2048);
#pragma unroll
        for (int i = 0; i < 4; i++) {
            int row = bm + warpm * 64 + i * 16 + g;
#pragma unroll
            for (int j = 0; j < 4; j++) {
                int col  = bn + warpn * 32 + j * 8 + 2 * tg;
                int colp = col >> 1;
                uint32_t h0, l0, h1, l1;
                split2(acc[i][j][0] * sc, acc[i][j][1] * sc, h0, l0);
                split2(acc[i][j][2] * sc, acc[i][j][3] * sc, h1, l1);
                g_qkvh[(size_t)row * KQ + colp]       = h0;
                g_qkvl[(size_t)row * KQ + colp]       = l0;
                g_qkvh[(size_t)(row + 8) * KQ + colp] = h1;
                g_qkvl[(size_t)(row + 8) * KQ + colp] = l1;
                if (wv) {
                    *(float2*)&g_qkv[(size_t)row * QKVD + col]       = make_float2(acc[i][j][0], acc[i][j][1]);
                    *(float2*)&g_qkv[(size_t)(row + 8) * QKVD + col] = make_float2(acc[i][j][2], acc[i][j][3]);
                }
            }
        }
    }
}

// ---------------------------------------------------------------------------
// Causal flash attention — GEMM-style tiles: [64 rows][128B], chunk swizzle
// c' = c ^ (row&7); ALL staging via cp.async (rows are 128B-contiguous in
// gmem); ALL fragment loads via ldmatrix.x4. 48KB smem, 3 CTAs/SM.
// Tiles (u32 offsets): Qh 0, Ql 2048, Kh 4096, Kl 6144, Vh 8192, Vl 10240.
// ---------------------------------------------------------------------------
#define AQ_H 0
#define AQ_L 2048
#define AK_H 4096
#define AK_L 6144
#define AV_H 8192
#define AV_L 10240
#define AT_SMEM (12288 * 4)

__global__ __launch_bounds__(128, 3)
void attn_mma() {
    extern __shared__ uint32_t sm[];
    const uint32_t sb = smem_u32(sm);

    const int tid  = threadIdx.x;
    const int lane = tid & 31;
    const int wid  = tid >> 5;
    const int g    = lane >> 2;
    const int tg   = lane & 3;
    const int rb   = wid << 4;
    const int qb   = blockIdx.x;
    const int h    = blockIdx.y;
    const int b    = blockIdx.z;

    // staging: thread = (row, 4 chunks of 16B)
    const int srow  = tid >> 1;          // 0..63
    const int shalf = tid & 1;
    const int ssw   = srow & 7;
    uint32_t dstc[4];
#pragma unroll
    for (int i = 0; i < 4; i++)
        dstc[i] = (uint32_t)srow * 128 + 16 * ((shalf * 4 + i) ^ ssw);

    // ldmatrix lane addressing
    const int rQ  = rb + (lane & 15);
    const int swQ = rQ & 7;
    const int cA  = lane >> 4;
    const int laB = (lane & 7) + ((lane >> 4) << 3);   // row within 16-block
    const int cB  = (lane >> 3) & 1;

    // ---- stage Q (pre-scaled hi/lo; 128B rows contiguous in gmem) ----
    {
        size_t qrow = (size_t)(b * SEQ + qb * 64 + srow) * KQ + h * 32;
#pragma unroll
        for (int i = 0; i < 4; i++) {
            cp16(sb + AQ_H * 4 + dstc[i], g_qkvh + qrow + (shalf * 4 + i) * 4);
            cp16(sb + AQ_L * 4 + dstc[i], g_qkvl + qrow + (shalf * 4 + i) * 4);
        }
        CP_COMMIT();
    }

    float m0 = -1e30f, m1 = -1e30f, l0s = 0.f, l1s = 0.f;
    float oacc[8][4];
#pragma unroll
    for (int j = 0; j < 8; j++)
#pragma unroll
        for (int q = 0; q < 4; q++) oacc[j][q] = 0.f;

    for (int kb = 0; kb <= qb; kb++) {
        __syncthreads();   // previous iteration done reading K/V

        // ---- stage K and V^T hi/lo via cp.async ----
        {
            size_t krow  = (size_t)(b * SEQ + kb * 64 + srow) * KQ + 512 + h * 32;
            size_t vrow  = ((size_t)(b * NH + h) * HD + srow) * (SEQ / 2) + kb * 32;
#pragma unroll
            for (int i = 0; i < 4; i++) {
                cp16(sb + AK_H * 4 + dstc[i], g_qkvh + krow + (shalf * 4 + i) * 4);
                cp16(sb + AK_L * 4 + dstc[i], g_qkvl + krow + (shalf * 4 + i) * 4);
                cp16(sb + AV_H * 4 + dstc[i], g_vth  + vrow + (shalf * 4 + i) * 4);
                cp16(sb + AV_L * 4 + dstc[i], g_vtl  + vrow + (shalf * 4 + i) * 4);
            }
            CP_COMMIT();
        }
        cp_wait<0>();
        __syncthreads();

        // ---- S = Q K^T, 3-term, ldmatrix fragments ----
        float sacc[8][4];
#pragma unroll
        for (int j = 0; j < 8; j++)
#pragma unroll
            for (int q = 0; q < 4; q++) sacc[j][q] = 0.f;

#pragma unroll
        for (int c = 0; c < 4; c++) {
            uint32_t ah[4], al[4];
            const uint32_t aoff = (uint32_t)rQ * 128 + 16 * ((2 * c + cA) ^ swQ);
            ldsm4(ah, sb + AQ_H * 4 + aoff);
            ldsm4(al, sb + AQ_L * 4 + aoff);

            uint32_t kh[4][4], kl[4][4];
#pragma unroll
            for (int jb = 0; jb < 4; jb++) {
                int row = jb * 16 + laB;
                uint32_t boff = (uint32_t)row * 128 + 16 * ((2 * c + cB) ^ (row & 7));
                ldsm4(kh[jb], sb + AK_H * 4 + boff);
                ldsm4(kl[jb], sb + AK_L * 4 + boff);
            }
#pragma unroll
            for (int jb = 0; jb < 4; jb++) {
                mma_bf16(sacc[2 * jb],     ah, &kh[jb][0]);
                mma_bf16(sacc[2 * jb + 1], ah, &kh[jb][2]);
            }
#pragma unroll
            for (int jb = 0; jb < 4; jb++) {
                mma_bf16(sacc[2 * jb],     ah, &kl[jb][0]);
                mma_bf16(sacc[2 * jb + 1], ah, &kl[jb][2]);
            }
#pragma unroll
            for (int jb = 0; jb < 4; jb++) {
                mma_bf16(sacc[2 * jb],     al, &kh[jb][0]);
                mma_bf16(sacc[2 * jb + 1], al, &kh[jb][2]);
            }
        }

        // ---- causal mask on diagonal block ----
        if (kb == qb) {
            const int r0 = rb + g, r1 = rb + g + 8;
#pragma unroll
            for (int j = 0; j < 8; j++) {
                int col = j * 8 + 2 * tg;
                if (col     > r0) sacc[j][0] = -1e30f;
                if (col + 1 > r0) sacc[j][1] = -1e30f;
                if (col     > r1) sacc[j][2] = -1e30f;
                if (col + 1 > r1) sacc[j][3] = -1e30f;
            }
        }

        // ---- online softmax ----
        float mx0 = -1e30f, mx1 = -1e30f;
#pragma unroll
        for (int j = 0; j < 8; j++) {
            mx0 = fmaxf(mx0, fmaxf(sacc[j][0], sacc[j][1]));
            mx1 = fmaxf(mx1, fmaxf(sacc[j][2], sacc[j][3]));
        }
        mx0 = fmaxf(mx0, __shfl_xor_sync(0xffffffffu, mx0, 1));
        mx0 = fmaxf(mx0, __shfl_xor_sync(0xffffffffu, mx0, 2));
        mx1 = fmaxf(mx1, __shfl_xor_sync(0xffffffffu, mx1, 1));
        mx1 = fmaxf(mx1, __shfl_xor_sync(0xffffffffu, mx1, 2));

        float mn0 = fmaxf(m0, mx0), mn1 = fmaxf(m1, mx1);
        float al0 = __expf(m0 - mn0), al1 = __expf(m1 - mn1);
        m0 = mn0; m1 = mn1;

        float rs0 = 0.f, rs1 = 0.f;
#pragma unroll
        for (int j = 0; j < 8; j++) {
            sacc[j][0] = __expf(sacc[j][0] - mn0); rs0 += sacc[j][0];
            sacc[j][1] = __expf(sacc[j][1] - mn0); rs0 += sacc[j][1];
            sacc[j][2] = __expf(sacc[j][2] - mn1); rs1 += sacc[j][2];
            sacc[j][3] = __expf(sacc[j][3] - mn1); rs1 += sacc[j][3];
        }
        rs0 += __shfl_xor_sync(0xffffffffu, rs0, 1);
        rs0 += __shfl_xor_sync(0xffffffffu, rs0, 2);
        rs1 += __shfl_xor_sync(0xffffffffu, rs1, 1);
        rs1 += __shfl_xor_sync(0xffffffffu, rs1, 2);
        l0s = l0s * al0 + rs0;
        l1s = l1s * al1 + rs1;

#pragma unroll
        for (int j = 0; j < 8; j++) {
            oacc[j][0] *= al0; oacc[j][1] *= al0;
            oacc[j][2] *= al1; oacc[j][3] *= al1;
        }

        // ---- O += P V, 3-term; P from registers, V via ldmatrix ----
#pragma unroll
        for (int cc = 0; cc < 4; cc++) {
            uint32_t ph[4], pl[4];
            split2(sacc[2 * cc][0],     sacc[2 * cc][1],     ph[0], pl[0]);
            split2(sacc[2 * cc][2],     sacc[2 * cc][3],     ph[1], pl[1]);
            split2(sacc[2 * cc + 1][0], sacc[2 * cc + 1][1], ph[2], pl[2]);
            split2(sacc[2 * cc + 1][2], sacc[2 * cc + 1][3], ph[3], pl[3]);

            uint32_t vh[4][4], vl[4][4];
#pragma unroll
            for (int db = 0; db < 4; db++) {
                int row = db * 16 + laB;
                uint32_t boff = (uint32_t)row * 128 + 16 * ((2 * cc + cB) ^ (row & 7));
                ldsm4(vh[db], sb + AV_H * 4 + boff);
                ldsm4(vl[db], sb + AV_L * 4 + boff);
            }
#pragma unroll
            for (int db = 0; db < 4; db++) {
                mma_bf16(oacc[2 * db],     ph, &vh[db][0]);
                mma_bf16(oacc[2 * db],     pl, &vh[db][0]);
                mma_bf16(oacc[2 * db],     ph, &vl[db][0]);
                mma_bf16(oacc[2 * db + 1], ph, &vh[db][2]);
                mma_bf16(oacc[2 * db + 1], pl, &vh[db][2]);
                mma_bf16(oacc[2 * db + 1], ph, &vl[db][2]);
            }
        }
    }

    // ---- finalize: write hi/lo bf16x2 directly for GEMM2 ----
    const float inv0 = 1.0f / l0s, inv1 = 1.0f / l1s;
    const size_t row0 = (size_t)(b * SEQ + qb * 64 + rb + g);
#pragma unroll
    for (int j2 = 0; j2 < 8; j2++) {
        uint32_t h0, l0, h1, l1;
        split2(oacc[j2][0] * inv0, oacc[j2][1] * inv0, h0, l0);
        split2(oacc[j2][2] * inv1, oacc[j2][3] * inv1, h1, l1);
        size_t idx0 = row0 * KH + h * 32 + j2 * 4 + tg;
        g_ah[idx0]            = h0;
        g_al[idx0]            = l0;
        g_ah[idx0 + 8 * KH]   = h1;
        g_al[idx0 + 8 * KH]   = l1;
    }
}

// ---------------------------------------------------------------------------
// launch
// ---------------------------------------------------------------------------
extern "C" void kernel_launch(void* const* d_in, const int* in_sizes, int n_in,
                              void* d_out, int out_size) {
    const float* x    = (const float*)d_in[0];   // [4,2048,1024]
    const float* Wqkv = (const float*)d_in[1];   // [3072,1024]
    const float* Wout = (const float*)d_in[2];   // [1024,1024]
    float*       out  = (float*)d_out;           // [4,2048,1024]

    uint32_t *xh, *xl, *wqh, *wql, *woh, *wol, *ah, *al;
    cudaGetSymbolAddress((void**)&xh,  g_xh);
    cudaGetSymbolAddress((void**)&xl,  g_xl);
    cudaGetSymbolAddress((void**)&wqh, g_wqh);
    cudaGetSymbolAddress((void**)&wql, g_wql);
    cudaGetSymbolAddress((void**)&woh, g_woh);
    cudaGetSymbolAddress((void**)&wol, g_wol);
    cudaGetSymbolAddress((void**)&ah,  g_ah);
    cudaGetSymbolAddress((void**)&al,  g_al);

    cudaFuncSetAttribute(gemm_bf3<0>, cudaFuncAttributeMaxDynamicSharedMemorySize, GT_SMEM);
    cudaFuncSetAttribute(gemm_bf3<1>, cudaFuncAttributeMaxDynamicSharedMemorySize, GT_SMEM);
    cudaFuncSetAttribute(attn_mma,    cudaFuncAttributeMaxDynamicSharedMemorySize, AT_SMEM);

    // 0) split inputs
    const int n2x = ROWS * KH;
    const int n2q = QKVD * KH;
    const int n2o = DIMX * KH;
    cvt_split<<<n2x / 256, 256>>>(x,    xh,  xl,  n2x);
    cvt_split<<<n2q / 256, 256>>>(Wqkv, wqh, wql, n2q);
    cvt_split<<<n2o / 256, 256>>>(Wout, woh, wol, n2o);

    // 1) qkv = x @ Wqkv^T — fused epilogue writes split hi/lo (+ fp32 V third)
    dim3 g1(QKVD / 128, ROWS / 128);
    gemm_bf3<1><<<g1, 256, GT_SMEM>>>(xh, xl, wqh, wql, nullptr, ROWS, QKVD, DIMX);

    // 1b) build transposed V hi/lo
    dim3 gv(SEQ / 32, BATCH * NH);
    cvt_vT<<<gv, 256>>>();

    // 2) causal attention -> g_ah/g_al (bf16x2 hi/lo)
    dim3 g2(SEQ / 64, NH, BATCH);
    attn_mma<<<g2, 128, AT_SMEM>>>();

    // 3) out = att @ Wout^T [8192,1024]
    dim3 g3(DIMX / 128, ROWS / 128);
    gemm_bf3<0><<<g3, 256, GT_SMEM>>>(ah, al, woh, wol, out, ROWS, DIMX, DIMX);
}